// round 9
// baseline (speedup 1.0000x reference)
#include <cuda_runtime.h>
#include <cuda_bf16.h>
#include <cuda_fp16.h>
#include <math.h>
#include <stdint.h>

#define NHEADS 4
#define HD 32
#define DDIM 128
#define MAXN 40000
#define MAXE 640000
#define MAXR 64
#define MAXB4 ((MAXN + 1023) / 1024)

// ---------------- scratch (device globals; no allocation) ----------------
__device__ __align__(16) __half g_h[MAXN * DDIM];   // projected entities (fp16)
__device__ __align__(16) float g_asrc[MAXN * NHEADS];
__device__ __align__(16) float g_adst[MAXN * NHEADS];
__device__ __align__(16) float g_arel[MAXR * NHEADS];
__device__ __align__(16) float g_cscore[MAXE * NHEADS]; // raw leaky scores, CSR order
__device__ int g_srcs[MAXE];
__device__ __align__(16) int g_deg[MAXN];
__device__ int g_rowptr[MAXN + 1];
__device__ int g_cursor[MAXN];
__device__ int g_bsum[256];
__device__ unsigned int g_maxenc;

__device__ __forceinline__ unsigned int enc_f(float f) {
    unsigned int u = __float_as_uint(f);
    return (u & 0x80000000u) ? ~u : (u | 0x80000000u);
}
__device__ __forceinline__ float dec_f(unsigned int u) {
    return __uint_as_float((u & 0x80000000u) ? (u & 0x7FFFFFFFu) : ~u);
}

// ================= mma.sync bf16 projection GEMM =================
#define ST 136  // smem row stride in halves (word-stride 68 -> conflict-free)

__device__ __forceinline__ void mma16816(float* d, const uint32_t* a,
                                         uint32_t b0, uint32_t b1) {
    asm volatile(
        "mma.sync.aligned.m16n8k16.row.col.f32.bf16.bf16.f32 "
        "{%0,%1,%2,%3}, {%4,%5,%6,%7}, {%8,%9}, {%0,%1,%2,%3};"
        : "+f"(d[0]), "+f"(d[1]), "+f"(d[2]), "+f"(d[3])
        : "r"(a[0]), "r"(a[1]), "r"(a[2]), "r"(a[3]), "r"(b0), "r"(b1));
}

__device__ __forceinline__ void split4(__nv_bfloat16* hi, __nv_bfloat16* lo,
                                       int off, float4 v) {
    __nv_bfloat16 hx = __float2bfloat16(v.x);
    __nv_bfloat16 hy = __float2bfloat16(v.y);
    __nv_bfloat16 hz = __float2bfloat16(v.z);
    __nv_bfloat16 hw = __float2bfloat16(v.w);
    *(__nv_bfloat162*)&hi[off]     = __halves2bfloat162(hx, hy);
    *(__nv_bfloat162*)&hi[off + 2] = __halves2bfloat162(hz, hw);
    *(__nv_bfloat162*)&lo[off] =
        __halves2bfloat162(__float2bfloat16(v.x - __bfloat162float(hx)),
                           __float2bfloat16(v.y - __bfloat162float(hy)));
    *(__nv_bfloat162*)&lo[off + 2] =
        __halves2bfloat162(__float2bfloat16(v.z - __bfloat162float(hz)),
                           __float2bfloat16(v.w - __bfloat162float(hw)));
}

#define SM_AHI 0
#define SM_ALO (128 * ST)
#define SM_WHI (2 * 128 * ST)
#define SM_WLO (3 * 128 * ST)
#define SM_HALVES (4 * 128 * ST)
#define SM_BYTES (SM_HALVES * 2)

__global__ void __launch_bounds__(256, 1)
k_proj_mma(const float* __restrict__ ent, const float* __restrict__ W,
           const float* __restrict__ attn_w, int Nn)
{
    extern __shared__ __nv_bfloat16 sm[];
    const int tid = threadIdx.x;
    const int warp = tid >> 5;
    const int lane = tid & 31;
    const int quad = lane >> 2;
    const int tq = lane & 3;
    const int n0 = blockIdx.x * 128;

    for (int i = tid; i < 4096; i += 256) {
        int flat = i * 4;
        int row = flat >> 7;
        int col = flat & 127;
        int off = row * ST + col;
        float4 wv = *(const float4*)&W[row * DDIM + col];
        split4(sm + SM_WHI, sm + SM_WLO, off, wv);
        int gn = n0 + row;
        float4 ev = make_float4(0.f, 0.f, 0.f, 0.f);
        if (gn < Nn) ev = *(const float4*)&ent[gn * DDIM + col];
        split4(sm + SM_AHI, sm + SM_ALO, off, ev);
    }
    __syncthreads();

    float acc[16][4];
#pragma unroll
    for (int j = 0; j < 16; j++)
#pragma unroll
        for (int c = 0; c < 4; c++) acc[j][c] = 0.f;

    const int r0 = warp * 16 + quad;
    const int r1 = r0 + 8;

#pragma unroll
    for (int ks = 0; ks < 8; ks++) {
        const int kb = ks * 16 + tq * 2;
        uint32_t ah[4], al[4];
        ah[0] = *(const uint32_t*)&sm[SM_AHI + r0 * ST + kb];
        ah[1] = *(const uint32_t*)&sm[SM_AHI + r1 * ST + kb];
        ah[2] = *(const uint32_t*)&sm[SM_AHI + r0 * ST + kb + 8];
        ah[3] = *(const uint32_t*)&sm[SM_AHI + r1 * ST + kb + 8];
        al[0] = *(const uint32_t*)&sm[SM_ALO + r0 * ST + kb];
        al[1] = *(const uint32_t*)&sm[SM_ALO + r1 * ST + kb];
        al[2] = *(const uint32_t*)&sm[SM_ALO + r0 * ST + kb + 8];
        al[3] = *(const uint32_t*)&sm[SM_ALO + r1 * ST + kb + 8];
#pragma unroll
        for (int j = 0; j < 16; j++) {
            int wr = (j * 8 + quad) * ST + kb;
            uint32_t bh0 = *(const uint32_t*)&sm[SM_WHI + wr];
            uint32_t bh1 = *(const uint32_t*)&sm[SM_WHI + wr + 8];
            uint32_t bl0 = *(const uint32_t*)&sm[SM_WLO + wr];
            uint32_t bl1 = *(const uint32_t*)&sm[SM_WLO + wr + 8];
            mma16816(acc[j], ah, bh0, bh1);
            mma16816(acc[j], ah, bl0, bl1);
            mma16816(acc[j], al, bh0, bh1);
        }
    }

    const int g0 = n0 + r0;
    const int g1 = n0 + r1;
    float s0[4] = {0, 0, 0, 0}, s1[4] = {0, 0, 0, 0};
    float t0[4] = {0, 0, 0, 0}, t1[4] = {0, 0, 0, 0};
#pragma unroll
    for (int j = 0; j < 16; j++) {
        int d0 = 8 * j + 2 * tq;
        int hh = j >> 2;
        int m = d0 & 31;
        float w0 = __ldg(&attn_w[m]);
        float w1 = __ldg(&attn_w[m + 1]);
        float v0 = __ldg(&attn_w[64 + m]);
        float v1 = __ldg(&attn_w[64 + m + 1]);
        s0[hh] += acc[j][0] * w0 + acc[j][1] * w1;
        t0[hh] += acc[j][0] * v0 + acc[j][1] * v1;
        s1[hh] += acc[j][2] * w0 + acc[j][3] * w1;
        t1[hh] += acc[j][2] * v0 + acc[j][3] * v1;
        if (g0 < Nn) *(half2*)&g_h[g0 * DDIM + d0] = __floats2half2_rn(acc[j][0], acc[j][1]);
        if (g1 < Nn) *(half2*)&g_h[g1 * DDIM + d0] = __floats2half2_rn(acc[j][2], acc[j][3]);
    }
#pragma unroll
    for (int off = 1; off < 4; off <<= 1) {
#pragma unroll
        for (int hh = 0; hh < 4; hh++) {
            s0[hh] += __shfl_xor_sync(0xffffffffu, s0[hh], off);
            s1[hh] += __shfl_xor_sync(0xffffffffu, s1[hh], off);
            t0[hh] += __shfl_xor_sync(0xffffffffu, t0[hh], off);
            t1[hh] += __shfl_xor_sync(0xffffffffu, t1[hh], off);
        }
    }
    if (tq == 0) {
        if (g0 < Nn) {
            *(float4*)&g_asrc[g0 * 4] = make_float4(s0[0], s0[1], s0[2], s0[3]);
            *(float4*)&g_adst[g0 * 4] = make_float4(t0[0], t0[1], t0[2], t0[3]);
        }
        if (g1 < Nn) {
            *(float4*)&g_asrc[g1 * 4] = make_float4(s1[0], s1[1], s1[2], s1[3]);
            *(float4*)&g_adst[g1 * 4] = make_float4(t1[0], t1[1], t1[2], t1[3]);
        }
    }
}

// ------- relation projection -> a_rel; also zero deg histogram + max -------
__global__ void k_proj_rel(const float* __restrict__ rel, const float* __restrict__ Wr,
                           const float* __restrict__ attn_w, int N, int R)
{
    int r = blockIdx.x;
    int t = threadIdx.x;
    int gid = r * blockDim.x + t;
    for (int i = gid; i < N; i += R * blockDim.x) g_deg[i] = 0;
    if (gid == 0) g_maxenc = 0u;

    const float* wr = Wr + t * DDIM;
    const float* rr = rel + r * DDIM;
    float dot = 0.f;
#pragma unroll
    for (int k = 0; k < DDIM; k += 4) {
        float4 a = *(const float4*)&wr[k];
        float4 b = *(const float4*)&rr[k];
        dot += a.x * b.x + a.y * b.y + a.z * b.z + a.w * b.w;
    }
    float val = dot * __ldg(&attn_w[32 + (t & 31)]);
#pragma unroll
    for (int off = 16; off >= 1; off >>= 1)
        val += __shfl_xor_sync(0xffffffffu, val, off);
    if ((t & 31) == 0) g_arel[r * 4 + (t >> 5)] = val;
}

// ---------------- dst-degree histogram (independent of projections) --------
__global__ __launch_bounds__(256) void k_deg(const int* __restrict__ ei, int E)
{
    int e = blockIdx.x * 256 + threadIdx.x;
    if (e < E) atomicAdd(&g_deg[__ldg(&ei[E + e])], 1);
}

// ------- scan pass 1: 4 elements/thread, shfl warp scans -------
__global__ __launch_bounds__(256) void k_scan1(int N)
{
    __shared__ int wsum[8];
    int tid = threadIdx.x;
    int lane = tid & 31;
    int warp = tid >> 5;
    int b4 = blockIdx.x * 1024 + tid * 4;
    int4 v = make_int4(0, 0, 0, 0);
    if (b4 + 3 < N) v = *(const int4*)&g_deg[b4];
    else if (b4 < N) {
        v.x = g_deg[b4];
        if (b4 + 1 < N) v.y = g_deg[b4 + 1];
        if (b4 + 2 < N) v.z = g_deg[b4 + 2];
    }
    int p0 = v.x, p1 = p0 + v.y, p2 = p1 + v.z, p3 = p2 + v.w;
    int inc = p3;
#pragma unroll
    for (int off = 1; off < 32; off <<= 1) {
        int t = __shfl_up_sync(0xffffffffu, inc, off);
        if (lane >= off) inc += t;
    }
    if (lane == 31) wsum[warp] = inc;
    __syncthreads();
    if (warp == 0 && lane < 8) {
        int w = wsum[lane];
#pragma unroll
        for (int off = 1; off < 8; off <<= 1) {
            int t = __shfl_up_sync(0xffu, w, off);
            if (lane >= off) w += t;
        }
        wsum[lane] = w;
        if (lane == 7) g_bsum[blockIdx.x] = w;
    }
    __syncthreads();
    int base = (warp > 0 ? wsum[warp - 1] : 0) + (inc - p3);
    if (b4 < N) {
        g_rowptr[b4] = base;
        if (b4 + 1 < N) g_rowptr[b4 + 1] = base + p0;
        if (b4 + 2 < N) g_rowptr[b4 + 2] = base + p1;
        if (b4 + 3 < N) g_rowptr[b4 + 3] = base + p2;
    }
}

// scan pass 2: every block redundantly scans block sums, applies, inits cursor
__global__ __launch_bounds__(256) void k_scan2(int N, int E, int nb)
{
    __shared__ int s[256];
    int tid = threadIdx.x;
    int v = (tid < nb) ? g_bsum[tid] : 0;
    s[tid] = v;
    __syncthreads();
#pragma unroll
    for (int off = 1; off < 256; off <<= 1) {
        int t = (tid >= off) ? s[tid - off] : 0;
        __syncthreads();
        s[tid] += t;
        __syncthreads();
    }
    __shared__ int boff;
    if (tid == blockIdx.x) boff = s[tid] - v;
    __syncthreads();
    int i0 = blockIdx.x * 1024 + tid * 4;
#pragma unroll
    for (int k = 0; k < 4; k++) {
        int i = i0 + k;
        if (i < N) {
            int val = g_rowptr[i] + boff;
            g_rowptr[i] = val;
            g_cursor[i] = val;
        }
    }
    if (blockIdx.x == 0 && tid == 0) g_rowptr[N] = E;
}

// ------- scores: gather terms, leaky, write RAW score to CSR pos, max -------
__global__ __launch_bounds__(256) void k_scores(
    const int* __restrict__ ei, const int* __restrict__ et,
    const float* __restrict__ attn_b, int E)
{
    int e = blockIdx.x * 256 + threadIdx.x;
    float lmax = -INFINITY;
    if (e < E) {
        int src = ei[e];
        int dst = ei[E + e];
        int r = et[e];
        float b = __ldg(attn_b);
        float4 a1 = *(const float4*)&g_asrc[src * 4];
        float4 a2 = *(const float4*)&g_arel[r * 4];
        float4 a3 = *(const float4*)&g_adst[dst * 4];
        float4 x;
        x.x = a1.x + a2.x + a3.x + b;
        x.y = a1.y + a2.y + a3.y + b;
        x.z = a1.z + a2.z + a3.z + b;
        x.w = a1.w + a2.w + a3.w + b;
        x.x = (x.x >= 0.f) ? x.x : 0.2f * x.x;
        x.y = (x.y >= 0.f) ? x.y : 0.2f * x.y;
        x.z = (x.z >= 0.f) ? x.z : 0.2f * x.z;
        x.w = (x.w >= 0.f) ? x.w : 0.2f * x.w;
        int pos = atomicAdd(&g_cursor[dst], 1);
        g_srcs[pos] = src;
        *(float4*)&g_cscore[pos * 4] = x;
        lmax = fmaxf(fmaxf(x.x, x.y), fmaxf(x.z, x.w));
    }
#pragma unroll
    for (int off = 16; off >= 1; off >>= 1)
        lmax = fmaxf(lmax, __shfl_xor_sync(0xffffffffu, lmax, off));
    __shared__ float smax[8];
    if ((threadIdx.x & 31) == 0) smax[threadIdx.x >> 5] = lmax;
    __syncthreads();
    if (threadIdx.x == 0) {
        float m = smax[0];
#pragma unroll
        for (int i = 1; i < 8; i++) m = fmaxf(m, smax[i]);
        atomicMax(&g_maxenc, enc_f(m));
    }
}

// ------- gather output: one warp per node; exp computed by 8-lane leaders ---
__global__ __launch_bounds__(256) void k_out(float* __restrict__ out, int N)
{
    int gt = blockIdx.x * blockDim.x + threadIdx.x;
    int n = gt >> 5;
    int lane = gt & 31;
    if (n >= N) return;
    float m = dec_f(g_maxenc);
    int start = g_rowptr[n];
    int end = g_rowptr[n + 1];
    int head = lane >> 3;
    int leader = lane & 24;
    bool is_leader = (lane & 7) == 0;

    float4 acc = make_float4(0.f, 0.f, 0.f, 0.f);
    float se = 0.f;
#pragma unroll 4
    for (int i = start; i < end; i++) {
        int s = __ldg(&g_srcs[i]);
        float w = 0.f;
        if (is_leader) w = __expf(__ldg(&g_cscore[i * 4 + head]) - m);
        w = __shfl_sync(0xffffffffu, w, leader);
        se += w;
        uint2 hv = *(const uint2*)&g_h[s * DDIM + lane * 4];
        float2 f0 = __half22float2(*(const half2*)&hv.x);
        float2 f1 = __half22float2(*(const half2*)&hv.y);
        acc.x += w * f0.x;
        acc.y += w * f0.y;
        acc.z += w * f1.x;
        acc.w += w * f1.y;
    }
    float inv = 1.f / (se + 1e-8f);
    acc.x *= inv; acc.y *= inv; acc.z *= inv; acc.w *= inv;
    *(float4*)&out[n * DDIM + lane * 4] = acc;
}

// ---------------- launch ----------------
extern "C" void kernel_launch(void* const* d_in, const int* in_sizes, int n_in,
                              void* d_out, int out_size)
{
    const float* ent = (const float*)d_in[0];
    const float* rel = (const float*)d_in[1];
    const int* ei = (const int*)d_in[2];
    const int* et = (const int*)d_in[3];
    const float* W  = (const float*)d_in[4];
    const float* Wr = (const float*)d_in[5];
    const float* aw = (const float*)d_in[6];
    const float* ab = (const float*)d_in[7];
    float* out = (float*)d_out;

    int N = in_sizes[0] / DDIM;
    int R = in_sizes[1] / DDIM;
    int E = in_sizes[3];
    int nb4 = (N + 1023) / 1024;

    cudaFuncSetAttribute(k_proj_mma, cudaFuncAttributeMaxDynamicSharedMemorySize, SM_BYTES);

    k_proj_rel<<<R, DDIM>>>(rel, Wr, aw, N, R);
    k_deg<<<(E + 255) / 256, 256>>>(ei, E);
    k_scan1<<<nb4, 256>>>(N);
    k_scan2<<<nb4, 256>>>(N, E, nb4);
    k_proj_mma<<<(N + 127) / 128, 256, SM_BYTES>>>(ent, W, aw, N);
    k_scores<<<(E + 255) / 256, 256>>>(ei, et, ab, E);
    k_out<<<(N * 32 + 255) / 256, 256>>>(out, N);
}

// round 10
// speedup vs baseline: 1.0621x; 1.0621x over previous
#include <cuda_runtime.h>
#include <cuda_bf16.h>
#include <cuda_fp16.h>
#include <math.h>
#include <stdint.h>

#define NHEADS 4
#define HD 32
#define DDIM 128
#define MAXN 40000
#define MAXE 640000
#define MAXR 64

// ---------------- scratch (device globals; no allocation) ----------------
__device__ __align__(16) __half g_h[MAXN * DDIM];   // projected entities (fp16)
__device__ __align__(16) float g_asrc[MAXN * NHEADS];
__device__ __align__(16) float g_adst[MAXN * NHEADS];
__device__ __align__(16) float g_arel[MAXR * NHEADS];
__device__ __align__(16) float g_score[MAXE * NHEADS];  // raw scores, edge order
__device__ __align__(16) float g_cscore[MAXE * NHEADS]; // exp scores, CSR order
__device__ int g_srcs[MAXE];
__device__ int g_within[MAXE];
__device__ __align__(16) int g_deg[MAXN];
__device__ int g_rowptr[MAXN + 1];
__device__ int g_bsum[64];
__device__ unsigned int g_maxenc;

__device__ __forceinline__ unsigned int enc_f(float f) {
    unsigned int u = __float_as_uint(f);
    return (u & 0x80000000u) ? ~u : (u | 0x80000000u);
}
__device__ __forceinline__ float dec_f(unsigned int u) {
    return __uint_as_float((u & 0x80000000u) ? (u & 0x7FFFFFFFu) : ~u);
}

// ================= mma.sync bf16 projection GEMM =================
#define ST 136  // smem row stride in halves (word-stride 68 -> conflict-free)

__device__ __forceinline__ void mma16816(float* d, const uint32_t* a,
                                         uint32_t b0, uint32_t b1) {
    asm volatile(
        "mma.sync.aligned.m16n8k16.row.col.f32.bf16.bf16.f32 "
        "{%0,%1,%2,%3}, {%4,%5,%6,%7}, {%8,%9}, {%0,%1,%2,%3};"
        : "+f"(d[0]), "+f"(d[1]), "+f"(d[2]), "+f"(d[3])
        : "r"(a[0]), "r"(a[1]), "r"(a[2]), "r"(a[3]), "r"(b0), "r"(b1));
}

__device__ __forceinline__ void split4(__nv_bfloat16* hi, __nv_bfloat16* lo,
                                       int off, float4 v) {
    __nv_bfloat16 hx = __float2bfloat16(v.x);
    __nv_bfloat16 hy = __float2bfloat16(v.y);
    __nv_bfloat16 hz = __float2bfloat16(v.z);
    __nv_bfloat16 hw = __float2bfloat16(v.w);
    *(__nv_bfloat162*)&hi[off]     = __halves2bfloat162(hx, hy);
    *(__nv_bfloat162*)&hi[off + 2] = __halves2bfloat162(hz, hw);
    *(__nv_bfloat162*)&lo[off] =
        __halves2bfloat162(__float2bfloat16(v.x - __bfloat162float(hx)),
                           __float2bfloat16(v.y - __bfloat162float(hy)));
    *(__nv_bfloat162*)&lo[off + 2] =
        __halves2bfloat162(__float2bfloat16(v.z - __bfloat162float(hz)),
                           __float2bfloat16(v.w - __bfloat162float(hw)));
}

#define SM_AHI 0
#define SM_ALO (128 * ST)
#define SM_WHI (2 * 128 * ST)
#define SM_WLO (3 * 128 * ST)
#define SM_HALVES (4 * 128 * ST)
#define SM_BYTES (SM_HALVES * 2)

__global__ void __launch_bounds__(256, 1)
k_proj_mma(const float* __restrict__ ent, const float* __restrict__ W,
           const float* __restrict__ attn_w, int Nn)
{
    extern __shared__ __nv_bfloat16 sm[];
    const int tid = threadIdx.x;
    const int warp = tid >> 5;
    const int lane = tid & 31;
    const int quad = lane >> 2;
    const int tq = lane & 3;
    const int n0 = blockIdx.x * 128;

    for (int i = tid; i < 4096; i += 256) {
        int flat = i * 4;
        int row = flat >> 7;
        int col = flat & 127;
        int off = row * ST + col;
        float4 wv = *(const float4*)&W[row * DDIM + col];
        split4(sm + SM_WHI, sm + SM_WLO, off, wv);
        int gn = n0 + row;
        float4 ev = make_float4(0.f, 0.f, 0.f, 0.f);
        if (gn < Nn) ev = *(const float4*)&ent[gn * DDIM + col];
        split4(sm + SM_AHI, sm + SM_ALO, off, ev);
    }
    __syncthreads();

    float acc[16][4];
#pragma unroll
    for (int j = 0; j < 16; j++)
#pragma unroll
        for (int c = 0; c < 4; c++) acc[j][c] = 0.f;

    const int r0 = warp * 16 + quad;
    const int r1 = r0 + 8;

#pragma unroll
    for (int ks = 0; ks < 8; ks++) {
        const int kb = ks * 16 + tq * 2;
        uint32_t ah[4], al[4];
        ah[0] = *(const uint32_t*)&sm[SM_AHI + r0 * ST + kb];
        ah[1] = *(const uint32_t*)&sm[SM_AHI + r1 * ST + kb];
        ah[2] = *(const uint32_t*)&sm[SM_AHI + r0 * ST + kb + 8];
        ah[3] = *(const uint32_t*)&sm[SM_AHI + r1 * ST + kb + 8];
        al[0] = *(const uint32_t*)&sm[SM_ALO + r0 * ST + kb];
        al[1] = *(const uint32_t*)&sm[SM_ALO + r1 * ST + kb];
        al[2] = *(const uint32_t*)&sm[SM_ALO + r0 * ST + kb + 8];
        al[3] = *(const uint32_t*)&sm[SM_ALO + r1 * ST + kb + 8];
#pragma unroll
        for (int j = 0; j < 16; j++) {
            int wr = (j * 8 + quad) * ST + kb;
            uint32_t bh0 = *(const uint32_t*)&sm[SM_WHI + wr];
            uint32_t bh1 = *(const uint32_t*)&sm[SM_WHI + wr + 8];
            uint32_t bl0 = *(const uint32_t*)&sm[SM_WLO + wr];
            uint32_t bl1 = *(const uint32_t*)&sm[SM_WLO + wr + 8];
            mma16816(acc[j], ah, bh0, bh1);
            mma16816(acc[j], ah, bl0, bl1);
            mma16816(acc[j], al, bh0, bh1);
        }
    }

    const int g0 = n0 + r0;
    const int g1 = n0 + r1;
    float s0[4] = {0, 0, 0, 0}, s1[4] = {0, 0, 0, 0};
    float t0[4] = {0, 0, 0, 0}, t1[4] = {0, 0, 0, 0};
#pragma unroll
    for (int j = 0; j < 16; j++) {
        int d0 = 8 * j + 2 * tq;
        int hh = j >> 2;
        int m = d0 & 31;
        float w0 = __ldg(&attn_w[m]);
        float w1 = __ldg(&attn_w[m + 1]);
        float v0 = __ldg(&attn_w[64 + m]);
        float v1 = __ldg(&attn_w[64 + m + 1]);
        s0[hh] += acc[j][0] * w0 + acc[j][1] * w1;
        t0[hh] += acc[j][0] * v0 + acc[j][1] * v1;
        s1[hh] += acc[j][2] * w0 + acc[j][3] * w1;
        t1[hh] += acc[j][2] * v0 + acc[j][3] * v1;
        if (g0 < Nn) *(half2*)&g_h[g0 * DDIM + d0] = __floats2half2_rn(acc[j][0], acc[j][1]);
        if (g1 < Nn) *(half2*)&g_h[g1 * DDIM + d0] = __floats2half2_rn(acc[j][2], acc[j][3]);
    }
#pragma unroll
    for (int off = 1; off < 4; off <<= 1) {
#pragma unroll
        for (int hh = 0; hh < 4; hh++) {
            s0[hh] += __shfl_xor_sync(0xffffffffu, s0[hh], off);
            s1[hh] += __shfl_xor_sync(0xffffffffu, s1[hh], off);
            t0[hh] += __shfl_xor_sync(0xffffffffu, t0[hh], off);
            t1[hh] += __shfl_xor_sync(0xffffffffu, t1[hh], off);
        }
    }
    if (tq == 0) {
        if (g0 < Nn) {
            *(float4*)&g_asrc[g0 * 4] = make_float4(s0[0], s0[1], s0[2], s0[3]);
            *(float4*)&g_adst[g0 * 4] = make_float4(t0[0], t0[1], t0[2], t0[3]);
        }
        if (g1 < Nn) {
            *(float4*)&g_asrc[g1 * 4] = make_float4(s1[0], s1[1], s1[2], s1[3]);
            *(float4*)&g_adst[g1 * 4] = make_float4(t1[0], t1[1], t1[2], t1[3]);
        }
    }
}

// ------- relation projection -> a_rel; also zero deg histogram + max -------
__global__ void k_proj_rel(const float* __restrict__ rel, const float* __restrict__ Wr,
                           const float* __restrict__ attn_w, int N, int R)
{
    int r = blockIdx.x;
    int t = threadIdx.x;
    int gid = r * blockDim.x + t;
    for (int i = gid; i < N; i += R * blockDim.x) g_deg[i] = 0;
    if (gid == 0) g_maxenc = 0u;

    const float* wr = Wr + t * DDIM;
    const float* rr = rel + r * DDIM;
    float dot = 0.f;
#pragma unroll
    for (int k = 0; k < DDIM; k += 4) {
        float4 a = *(const float4*)&wr[k];
        float4 b = *(const float4*)&rr[k];
        dot += a.x * b.x + a.y * b.y + a.z * b.z + a.w * b.w;
    }
    float val = dot * __ldg(&attn_w[32 + (t & 31)]);
#pragma unroll
    for (int off = 16; off >= 1; off >>= 1)
        val += __shfl_xor_sync(0xffffffffu, val, off);
    if ((t & 31) == 0) g_arel[r * 4 + (t >> 5)] = val;
}

// ------- scores + global max + dst-degree histogram w/ within-rank -------
__device__ __forceinline__ float score_one(const int* ei, const int* et,
                                           float b, int e, int E) {
    int src = ei[e];
    int dst = ei[E + e];
    int r = et[e];
    float4 a1 = *(const float4*)&g_asrc[src * 4];
    float4 a2 = *(const float4*)&g_arel[r * 4];
    float4 a3 = *(const float4*)&g_adst[dst * 4];
    float4 x;
    x.x = a1.x + a2.x + a3.x + b;
    x.y = a1.y + a2.y + a3.y + b;
    x.z = a1.z + a2.z + a3.z + b;
    x.w = a1.w + a2.w + a3.w + b;
    x.x = (x.x >= 0.f) ? x.x : 0.2f * x.x;
    x.y = (x.y >= 0.f) ? x.y : 0.2f * x.y;
    x.z = (x.z >= 0.f) ? x.z : 0.2f * x.z;
    x.w = (x.w >= 0.f) ? x.w : 0.2f * x.w;
    *(float4*)&g_score[e * 4] = x;
    g_within[e] = atomicAdd(&g_deg[dst], 1);
    return fmaxf(fmaxf(x.x, x.y), fmaxf(x.z, x.w));
}

__global__ __launch_bounds__(256) void k_scores(
    const int* __restrict__ ei, const int* __restrict__ et,
    const float* __restrict__ attn_b, int E)
{
    int base = blockIdx.x * 512 + threadIdx.x;
    float b = __ldg(attn_b);
    float lmax = -INFINITY;
    if (base < E) lmax = score_one(ei, et, b, base, E);
    int e2 = base + 256;
    if (e2 < E) lmax = fmaxf(lmax, score_one(ei, et, b, e2, E));
#pragma unroll
    for (int off = 16; off >= 1; off >>= 1)
        lmax = fmaxf(lmax, __shfl_xor_sync(0xffffffffu, lmax, off));
    __shared__ float smax[8];
    if ((threadIdx.x & 31) == 0) smax[threadIdx.x >> 5] = lmax;
    __syncthreads();
    if (threadIdx.x == 0) {
        float m = smax[0];
#pragma unroll
        for (int i = 1; i < 8; i++) m = fmaxf(m, smax[i]);
        atomicMax(&g_maxenc, enc_f(m));
    }
}

// ------- scan pass 1: 4 elements/thread, shfl warp scans -------
__global__ __launch_bounds__(256) void k_scan1(int N)
{
    __shared__ int wsum[8];
    int tid = threadIdx.x;
    int lane = tid & 31;
    int warp = tid >> 5;
    int b4 = blockIdx.x * 1024 + tid * 4;
    int4 v = make_int4(0, 0, 0, 0);
    if (b4 + 3 < N) v = *(const int4*)&g_deg[b4];
    else if (b4 < N) {
        v.x = g_deg[b4];
        if (b4 + 1 < N) v.y = g_deg[b4 + 1];
        if (b4 + 2 < N) v.z = g_deg[b4 + 2];
    }
    int p0 = v.x, p1 = p0 + v.y, p2 = p1 + v.z, p3 = p2 + v.w;
    int inc = p3;
#pragma unroll
    for (int off = 1; off < 32; off <<= 1) {
        int t = __shfl_up_sync(0xffffffffu, inc, off);
        if (lane >= off) inc += t;
    }
    if (lane == 31) wsum[warp] = inc;
    __syncthreads();
    if (warp == 0 && lane < 8) {
        int w = wsum[lane];
#pragma unroll
        for (int off = 1; off < 8; off <<= 1) {
            int t = __shfl_up_sync(0xffu, w, off);
            if (lane >= off) w += t;
        }
        wsum[lane] = w;
        if (lane == 7) g_bsum[blockIdx.x] = w;
    }
    __syncthreads();
    int base = (warp > 0 ? wsum[warp - 1] : 0) + (inc - p3);
    if (b4 < N) {
        g_rowptr[b4] = base;
        if (b4 + 1 < N) g_rowptr[b4 + 1] = base + p0;
        if (b4 + 2 < N) g_rowptr[b4 + 2] = base + p1;
        if (b4 + 3 < N) g_rowptr[b4 + 3] = base + p2;
    }
}

// scan pass 2: direct smem sum of <=64 block sums, then apply (4/thread)
__global__ __launch_bounds__(256) void k_scan2(int N, int E, int nb)
{
    __shared__ int s[64];
    int tid = threadIdx.x;
    if (tid < 64) s[tid] = (tid < nb) ? g_bsum[tid] : 0;
    __syncthreads();
    int boff = 0;
    int bid = blockIdx.x;
    for (int k = 0; k < bid; k++) boff += s[k];  // <=63 LDS+IADD, uniform
    int i0 = blockIdx.x * 1024 + tid * 4;
#pragma unroll
    for (int k = 0; k < 4; k++) {
        int i = i0 + k;
        if (i < N) g_rowptr[i] += boff;
    }
    if (blockIdx.x == 0 && tid == 0) g_rowptr[N] = E;
}

// ---------------- scatter into CSR order, atomic-free ----------------
__device__ __forceinline__ void scatter_one(const int* ei, float m, int e, int E) {
    int src = ei[e];
    int dst = ei[E + e];
    int pos = g_rowptr[dst] + g_within[e];
    g_srcs[pos] = src;
    float4 s = *(const float4*)&g_score[e * 4];
    s.x = __expf(s.x - m);
    s.y = __expf(s.y - m);
    s.z = __expf(s.z - m);
    s.w = __expf(s.w - m);
    *(float4*)&g_cscore[pos * 4] = s;
}

__global__ __launch_bounds__(256) void k_scatter(const int* __restrict__ ei, int E)
{
    int base = blockIdx.x * 512 + threadIdx.x;
    float m = dec_f(g_maxenc);
    if (base < E) scatter_one(ei, m, base, E);
    int e2 = base + 256;
    if (e2 < E) scatter_one(ei, m, e2, E);
}

// ---------------- gather-only output: one warp per dst node ----------------
__global__ __launch_bounds__(256) void k_out(float* __restrict__ out, int N)
{
    int gt = blockIdx.x * blockDim.x + threadIdx.x;
    int n = gt >> 5;
    int lane = gt & 31;
    if (n >= N) return;
    int start = g_rowptr[n];
    int end = g_rowptr[n + 1];
    int head = lane >> 3;

    float4 acc = make_float4(0.f, 0.f, 0.f, 0.f);
    float se = 0.f;
#pragma unroll 4
    for (int i = start; i < end; i++) {
        int s = __ldg(&g_srcs[i]);
        float w = __ldg(&g_cscore[i * 4 + head]);
        se += w;
        uint2 hv = *(const uint2*)&g_h[s * DDIM + lane * 4];
        float2 f0 = __half22float2(*(const half2*)&hv.x);
        float2 f1 = __half22float2(*(const half2*)&hv.y);
        acc.x += w * f0.x;
        acc.y += w * f0.y;
        acc.z += w * f1.x;
        acc.w += w * f1.y;
    }
    float inv = 1.f / (se + 1e-8f);
    acc.x *= inv; acc.y *= inv; acc.z *= inv; acc.w *= inv;
    *(float4*)&out[n * DDIM + lane * 4] = acc;
}

// ---------------- launch ----------------
extern "C" void kernel_launch(void* const* d_in, const int* in_sizes, int n_in,
                              void* d_out, int out_size)
{
    const float* ent = (const float*)d_in[0];
    const float* rel = (const float*)d_in[1];
    const int* ei = (const int*)d_in[2];
    const int* et = (const int*)d_in[3];
    const float* W  = (const float*)d_in[4];
    const float* Wr = (const float*)d_in[5];
    const float* aw = (const float*)d_in[6];
    const float* ab = (const float*)d_in[7];
    float* out = (float*)d_out;

    int N = in_sizes[0] / DDIM;
    int R = in_sizes[1] / DDIM;
    int E = in_sizes[3];
    int nb4 = (N + 1023) / 1024;

    cudaFuncSetAttribute(k_proj_mma, cudaFuncAttributeMaxDynamicSharedMemorySize, SM_BYTES);

    k_proj_rel<<<R, DDIM>>>(rel, Wr, aw, N, R);
    k_proj_mma<<<(N + 127) / 128, 256, SM_BYTES>>>(ent, W, aw, N);
    k_scores<<<(E + 511) / 512, 256>>>(ei, et, ab, E);
    k_scan1<<<nb4, 256>>>(N);
    k_scan2<<<nb4, 256>>>(N, E, nb4);
    k_scatter<<<(E + 511) / 512, 256>>>(ei, E);
    k_out<<<(N * 32 + 255) / 256, 256>>>(out, N);
}